// round 1
// baseline (speedup 1.0000x reference)
#include <cuda_runtime.h>

#define T 4096
#define TMASK 4095
#define NTH 256
#define C 16   // samples per thread (NTH * C == T)

// Bank-conflict-killing swizzle: XOR bits [5:9) into bits [0:4).
// Conflict-free for: consecutive writes, stride-4 scatter (staging),
// stride-16 reads/writes (compute). Invariant under +/-4096 wrap.
__device__ __forceinline__ int sw(int w) { return w ^ ((w >> 5) & 15); }

// Stage 4096 floats global -> shared (swizzled). Coalesced float4 reads.
__device__ __forceinline__ void stage(float* s, const float* __restrict__ g, int tid) {
    const float4* g4 = (const float4*)g;
#pragma unroll
    for (int i = 0; i < T / 4 / NTH; ++i) {   // 4 iterations
        int idx = tid + i * NTH;
        float4 v = __ldg(&g4[idx]);
        int w = idx * 4;
        int m = (w >> 5) & 15;  // same mask for all 4 words (w % 32 < 29)
        s[(w + 0) ^ m] = v.x;
        s[(w + 1) ^ m] = v.y;
        s[(w + 2) ^ m] = v.z;
        s[(w + 3) ^ m] = v.w;
    }
}

// One ISWT synthesis level with dilation D.
// acc[j] = 0.5 * sum_m ( lo[m]*res[(n + D*(3-m)) & TMASK]
//                      + hi[m]*hi_arr[(n + D*(3-m)) & TMASK] ),  n = base + j
// Loop over input window elements u; each loaded value feeds up to 8 acc's.
template <int D>
__device__ __forceinline__ void level_compute(const float* sres, const float* shi,
                                              float* acc, int base) {
    // db4 synthesis filters, pre-scaled by 0.5 (the per-level factor)
    constexpr float LO[8] = {
        0.5f *  0.23037781330885523f, 0.5f *  0.7148465705525415f,
        0.5f *  0.6308807679295904f,  0.5f * -0.02798376941698385f,
        0.5f * -0.18703481171888114f, 0.5f *  0.030841381835986965f,
        0.5f *  0.032883011666982945f,0.5f * -0.010597401784997278f };
    // rec_hi[k] = (-1)^k * rec_lo[7-k], pre-scaled by 0.5
    constexpr float HI[8] = {
        0.5f * -0.010597401784997278f, 0.5f * -0.032883011666982945f,
        0.5f *  0.030841381835986965f, 0.5f *  0.18703481171888114f,
        0.5f * -0.02798376941698385f,  0.5f * -0.6308807679295904f,
        0.5f *  0.7148465705525415f,   0.5f * -0.23037781330885523f };

#pragma unroll
    for (int j = 0; j < C; ++j) acc[j] = 0.0f;

    // Low-pass path over previous-level result
#pragma unroll
    for (int u = -4 * D; u <= (C - 1) + 3 * D; ++u) {
        int w = (base + u) & TMASK;
        float v = sres[sw(w)];
#pragma unroll
        for (int m = 0; m < 8; ++m) {
            int j = u - D * (3 - m);
            if (j >= 0 && j < C) acc[j] += LO[m] * v;
        }
    }
    // High-pass path over this level's detail coefficients
#pragma unroll
    for (int u = -4 * D; u <= (C - 1) + 3 * D; ++u) {
        int w = (base + u) & TMASK;
        float v = shi[sw(w)];
#pragma unroll
        for (int m = 0; m < 8; ++m) {
            int j = u - D * (3 - m);
            if (j >= 0 && j < C) acc[j] += HI[m] * v;
        }
    }
}

__global__ void __launch_bounds__(NTH, 4)
iswt_kernel(const float* __restrict__ x, float* __restrict__ out) {
    __shared__ float sA[T];
    __shared__ float sB[T];
    __shared__ float sH[T];

    const int bn = blockIdx.x;                     // row in [0, 2048)
    const float* basep = x + (size_t)bn * 4 * T;   // cA | cD3 | cD2 | cD1 contiguous
    const int tid = threadIdx.x;
    const int base = tid * C;

    // Level 1 inputs: cA3 -> sA, cD3 -> sH
    stage(sA, basep + 0 * T, tid);
    stage(sH, basep + 1 * T, tid);
    __syncthreads();

    float acc[C];

    // Level 1: d = 4
    level_compute<4>(sA, sH, acc, base);
#pragma unroll
    for (int j = 0; j < C; ++j) sB[sw(base + j)] = acc[j];
    __syncthreads();               // level-1 reads of sA/sH done; sB writes visible

    stage(sH, basep + 2 * T, tid); // cD2
    __syncthreads();

    // Level 2: d = 2
    level_compute<2>(sB, sH, acc, base);
#pragma unroll
    for (int j = 0; j < C; ++j) sA[sw(base + j)] = acc[j];
    __syncthreads();

    stage(sH, basep + 3 * T, tid); // cD1
    __syncthreads();

    // Level 3: d = 1, write straight to global
    level_compute<1>(sA, sH, acc, base);
    float4* o = (float4*)(out + (size_t)bn * T + base);
#pragma unroll
    for (int q = 0; q < 4; ++q)
        o[q] = make_float4(acc[4 * q + 0], acc[4 * q + 1],
                           acc[4 * q + 2], acc[4 * q + 3]);
}

extern "C" void kernel_launch(void* const* d_in, const int* in_sizes, int n_in,
                              void* d_out, int out_size) {
    const float* x = (const float*)d_in[0];
    float* out = (float*)d_out;
    // 32 * 256 * 4096 input -> 2048 rows of 4 coeff arrays, T = 4096
    iswt_kernel<<<2048, NTH>>>(x, out);
}

// round 2
// speedup vs baseline: 1.3806x; 1.3806x over previous
#include <cuda_runtime.h>

#define T    4096
#define NTH  256
#define C    16          // samples per thread (NTH*C == T)

// Transposed-chunk shared layout: logical index li (= w + HL) stored at
//   phys = (li % 16) * W + (li / 16)
// Every thread's base is 16*tid, so for each compile-time window offset u the
// physical offset from (buf + tid) is a compile-time constant -> LDS [R+imm].
#define WA 258           // A,H: halo 16 left / 12 right  -> li in [0, 4124), cols <= 257
#define WB 257           // B:   halo  8 left /  6 right  -> li in [0, 4110), cols <= 256
#define WH 258

#define OFF_A 0
#define OFF_B (16 * WA)            // 4128
#define OFF_H (OFF_B + 16 * WB)    // 8240
#define SMEM_WORDS (OFF_H + 16 * WH)   // 12368
#define SMEM_BYTES (SMEM_WORDS * 4)    // 49472

// Stage one T-length array into a W=258 buffer with halo 16/12 (circular).
__device__ __forceinline__ void stage16(float* s, const float* __restrict__ g, int tid) {
    const float4* g4 = (const float4*)g;
#pragma unroll
    for (int i = 0; i < 4; ++i) {
        int idx = tid + i * NTH;                 // float4 index, li = 4*idx + 16
        float4 v = __ldg(&g4[idx]);
        int r = (idx & 3) * 4;                   // li % 16
        int q = (idx >> 2) + 1;                  // li / 16
        float* p = s + r * WA + q;
        p[0 * WA] = v.x; p[1 * WA] = v.y; p[2 * WA] = v.z; p[3 * WA] = v.w;
    }
    if (tid < 16) s[tid * WA]       = g[T - 16 + tid];   // li = tid        -> (tid,0)
    if (tid < 12) s[tid * WA + 257] = g[tid];            // li = 4112 + tid -> (tid,257)
}

// One ISWT synthesis level, dilation D.  res buffer has halo HL & width W;
// hi buffer always halo 16 / width WH.  All offsets compile-time.
template <int D, int HL, int W>
__device__ __forceinline__ void level(const float* __restrict__ sres,
                                      const float* __restrict__ shi,
                                      float* acc, int tid) {
    constexpr float LO[8] = {
        0.5f *  0.23037781330885523f, 0.5f *  0.7148465705525415f,
        0.5f *  0.6308807679295904f,  0.5f * -0.02798376941698385f,
        0.5f * -0.18703481171888114f, 0.5f *  0.030841381835986965f,
        0.5f *  0.032883011666982945f,0.5f * -0.010597401784997278f };
    constexpr float HI[8] = {
        0.5f * -0.010597401784997278f, 0.5f * -0.032883011666982945f,
        0.5f *  0.030841381835986965f, 0.5f *  0.18703481171888114f,
        0.5f * -0.02798376941698385f,  0.5f * -0.6308807679295904f,
        0.5f *  0.7148465705525415f,   0.5f * -0.23037781330885523f };

#pragma unroll
    for (int j = 0; j < C; ++j) acc[j] = 0.0f;

    const float* pr = sres + tid;
    const float* ph = shi + tid;

#pragma unroll
    for (int u = -4 * D; u <= C - 1 + 3 * D; ++u) {
        {
            constexpr int dummy = 0; (void)dummy;
            int li = u + HL;                       // >= 0 for every level
            float v = pr[(li & 15) * W + (li >> 4)];
#pragma unroll
            for (int m = 0; m < 8; ++m) {
                int j = u - D * (3 - m);
                if (j >= 0 && j < C) acc[j] = fmaf(LO[m], v, acc[j]);
            }
        }
        {
            int li = u + 16;
            float v = ph[(li & 15) * WH + (li >> 4)];
#pragma unroll
            for (int m = 0; m < 8; ++m) {
                int j = u - D * (3 - m);
                if (j >= 0 && j < C) acc[j] = fmaf(HI[m], v, acc[j]);
            }
        }
    }
}

// Write acc into buffer (halo HL, width W) and replicate the circular halo
// (HLN left / HRN right) needed by the next level's reads.
template <int HL, int W, int HLN, int HRN>
__device__ __forceinline__ void store_level(float* s, const float* acc, int tid) {
    float* p = s + tid;
#pragma unroll
    for (int j = 0; j < C; ++j) {
        int li = j + HL;
        p[(li & 15) * W + (li >> 4)] = acc[j];
    }
    if (tid == NTH - 1) {       // logical w in [T-HLN, T) also serves w-T in [-HLN,0)
#pragma unroll
        for (int j = C - HLN; j < C; ++j) {
            int li = (j - C) + HL;                 // in [0, HL)
            s[(li & 15) * W + (li >> 4)] = acc[j];
        }
    }
    if (tid == 0) {             // logical w in [0, HRN) also serves w+T
#pragma unroll
        for (int j = 0; j < HRN; ++j) {
            int li = T + j + HL;
            s[(li & 15) * W + (li >> 4)] = acc[j];
        }
    }
}

extern __shared__ float smem[];

__global__ void __launch_bounds__(NTH, 4)
iswt_kernel(const float* __restrict__ x, float* __restrict__ out) {
    float* sA = smem + OFF_A;
    float* sB = smem + OFF_B;
    float* sH = smem + OFF_H;

    const int bn  = blockIdx.x;                    // row in [0, 2048)
    const int tid = threadIdx.x;
    const float* g = x + (size_t)bn * 4 * T;       // cA | cD3 | cD2 | cD1

    stage16(sA, g + 0 * T, tid);                   // cA3
    stage16(sH, g + 1 * T, tid);                   // cD3
    __syncthreads();

    float acc[C];

    level<4, 16, WA>(sA, sH, acc, tid);            // level 1, d=4
    store_level<8, WB, 8, 6>(sB, acc, tid);
    __syncthreads();

    stage16(sH, g + 2 * T, tid);                   // cD2
    __syncthreads();

    level<2, 8, WB>(sB, sH, acc, tid);             // level 2, d=2
    store_level<4, WA, 4, 3>(sA, acc, tid);
    __syncthreads();

    stage16(sH, g + 3 * T, tid);                   // cD1
    __syncthreads();

    level<1, 4, WA>(sA, sH, acc, tid);             // level 3, d=1 -> global
    float4* o = (float4*)(out + (size_t)bn * T + tid * C);
#pragma unroll
    for (int q = 0; q < 4; ++q)
        o[q] = make_float4(acc[4 * q + 0], acc[4 * q + 1],
                           acc[4 * q + 2], acc[4 * q + 3]);
}

extern "C" void kernel_launch(void* const* d_in, const int* in_sizes, int n_in,
                              void* d_out, int out_size) {
    const float* x = (const float*)d_in[0];
    float* out = (float*)d_out;
    cudaFuncSetAttribute(iswt_kernel,
                         cudaFuncAttributeMaxDynamicSharedMemorySize, SMEM_BYTES);
    iswt_kernel<<<2048, NTH, SMEM_BYTES>>>(x, out);
}

// round 3
// speedup vs baseline: 1.3880x; 1.0054x over previous
#include <cuda_runtime.h>

#define T    4096
#define NTH  256
#define C    16          // samples per thread (NTH*C == T)
#define W    258         // unified buffer width; 258 % 8 == 2 -> staging conflict-free

// 4 buffers: A (result ping), B (result pong), H0 (cD3 then cD1), H1 (cD2)
#define BUFW  (16 * W)                 // 4128 words per buffer
#define OFF_A 0
#define OFF_B (1 * BUFW)
#define OFF_H0 (2 * BUFW)
#define OFF_H1 (3 * BUFW)
#define SMEM_WORDS (4 * BUFW)
#define SMEM_BYTES (SMEM_WORDS * 4)    // 66048

// Transposed-chunk layout: logical li stored at phys = (li%16)*W + (li/16).
// Thread bases are 16*tid, so all window offsets are compile-time immediates.

struct Pref { float4 v[4]; float hl, hr; };

__device__ __forceinline__ void prefetch(Pref& p, const float* __restrict__ g, int tid) {
    const float4* g4 = (const float4*)g;
#pragma unroll
    for (int i = 0; i < 4; ++i) p.v[i] = __ldg(&g4[tid + i * NTH]);
    p.hl = (tid < 16) ? __ldg(&g[T - 16 + tid]) : 0.0f;
    p.hr = (tid < 12) ? __ldg(&g[tid])          : 0.0f;
}

__device__ __forceinline__ void commit(float* s, const Pref& p, int tid) {
#pragma unroll
    for (int i = 0; i < 4; ++i) {
        int idx = tid + i * NTH;                 // float4 index; li = 4*idx + 16
        int r = (idx & 3) * 4;                   // li % 16
        int q = (idx >> 2) + 1;                  // li / 16
        float* d = s + r * W + q;
        d[0 * W] = p.v[i].x; d[1 * W] = p.v[i].y;
        d[2 * W] = p.v[i].z; d[3 * W] = p.v[i].w;
    }
    if (tid < 16) s[tid * W]       = p.hl;       // li = tid (left halo, 16)
    if (tid < 12) s[tid * W + 257] = p.hr;       // li = 4112 + tid (right halo, 12)
}

__device__ __forceinline__ void stage(float* s, const float* __restrict__ g, int tid) {
    Pref p; prefetch(p, g, tid); commit(s, p, tid);
}

// One ISWT synthesis level, dilation D; res buffer halo HL, hi buffer halo 16.
template <int D, int HL>
__device__ __forceinline__ void level(const float* __restrict__ sres,
                                      const float* __restrict__ shi,
                                      float* acc, int tid) {
    constexpr float LO[8] = {
        0.5f *  0.23037781330885523f, 0.5f *  0.7148465705525415f,
        0.5f *  0.6308807679295904f,  0.5f * -0.02798376941698385f,
        0.5f * -0.18703481171888114f, 0.5f *  0.030841381835986965f,
        0.5f *  0.032883011666982945f,0.5f * -0.010597401784997278f };
    constexpr float HI[8] = {
        0.5f * -0.010597401784997278f, 0.5f * -0.032883011666982945f,
        0.5f *  0.030841381835986965f, 0.5f *  0.18703481171888114f,
        0.5f * -0.02798376941698385f,  0.5f * -0.6308807679295904f,
        0.5f *  0.7148465705525415f,   0.5f * -0.23037781330885523f };

#pragma unroll
    for (int j = 0; j < C; ++j) acc[j] = 0.0f;

    const float* pr = sres + tid;
    const float* ph = shi + tid;

#pragma unroll
    for (int u = -4 * D; u <= C - 1 + 3 * D; ++u) {
        {
            int li = u + HL;
            float v = pr[(li & 15) * W + (li >> 4)];
#pragma unroll
            for (int m = 0; m < 8; ++m) {
                int j = u - D * (3 - m);
                if (j >= 0 && j < C) acc[j] = fmaf(LO[m], v, acc[j]);
            }
        }
        {
            int li = u + 16;
            float v = ph[(li & 15) * W + (li >> 4)];
#pragma unroll
            for (int m = 0; m < 8; ++m) {
                int j = u - D * (3 - m);
                if (j >= 0 && j < C) acc[j] = fmaf(HI[m], v, acc[j]);
            }
        }
    }
}

// Write acc (halo HL layout) + replicate circular halo HLN left / HRN right.
template <int HL, int HLN, int HRN>
__device__ __forceinline__ void store_level(float* s, const float* acc, int tid) {
    float* p = s + tid;
#pragma unroll
    for (int j = 0; j < C; ++j) {
        int li = j + HL;
        p[(li & 15) * W + (li >> 4)] = acc[j];
    }
    if (tid == NTH - 1) {
#pragma unroll
        for (int j = C - HLN; j < C; ++j) {
            int li = (j - C) + HL;
            s[(li & 15) * W + (li >> 4)] = acc[j];
        }
    }
    if (tid == 0) {
#pragma unroll
        for (int j = 0; j < HRN; ++j) {
            int li = T + j + HL;
            s[(li & 15) * W + (li >> 4)] = acc[j];
        }
    }
}

extern __shared__ float smem[];

__global__ void __launch_bounds__(NTH, 3)
iswt_kernel(const float* __restrict__ x, float* __restrict__ out) {
    float* sA  = smem + OFF_A;
    float* sB  = smem + OFF_B;
    float* sH0 = smem + OFF_H0;
    float* sH1 = smem + OFF_H1;

    const int bn  = blockIdx.x;                    // row in [0, 2048)
    const int tid = threadIdx.x;
    const float* g = x + (size_t)bn * 4 * T;       // cA3 | cD3 | cD2 | cD1

    // All global traffic issued up-front (max MLP, latency paid once)
    stage(sA,  g + 0 * T, tid);                    // cA3
    stage(sH0, g + 1 * T, tid);                    // cD3
    stage(sH1, g + 2 * T, tid);                    // cD2
    Pref pd1; prefetch(pd1, g + 3 * T, tid);       // cD1 -> registers
    __syncthreads();

    float acc[C];

    // Level 1: d=4, inputs A + H0 -> B (halo 8/6 for level 2)
    level<4, 16>(sA, sH0, acc, tid);
    store_level<8, 8, 6>(sB, acc, tid);
    __syncthreads();

    // H0 (cD3) fully consumed -> overwrite with cD1 while L2 computes
    commit(sH0, pd1, tid);

    // Level 2: d=2, inputs B + H1 -> A (halo 4/3 for level 3)
    level<2, 8>(sB, sH1, acc, tid);
    store_level<4, 4, 3>(sA, acc, tid);
    __syncthreads();

    // Level 3: d=1, inputs A + H0 -> global
    level<1, 4>(sA, sH0, acc, tid);
    float4* o = (float4*)(out + (size_t)bn * T + tid * C);
#pragma unroll
    for (int q = 0; q < 4; ++q)
        o[q] = make_float4(acc[4 * q + 0], acc[4 * q + 1],
                           acc[4 * q + 2], acc[4 * q + 3]);
}

extern "C" void kernel_launch(void* const* d_in, const int* in_sizes, int n_in,
                              void* d_out, int out_size) {
    const float* x = (const float*)d_in[0];
    float* out = (float*)d_out;
    cudaFuncSetAttribute(iswt_kernel,
                         cudaFuncAttributeMaxDynamicSharedMemorySize, SMEM_BYTES);
    iswt_kernel<<<2048, NTH, SMEM_BYTES>>>(x, out);
}